// round 7
// baseline (speedup 1.0000x reference)
#include <cuda_runtime.h>
#include <math.h>

#define NN 50000
#define EE 800000
#define BG 512
#define D  128

// ---------------- scratch (static device globals; no allocation) ----------------
__device__ int   g_deg[NN];
__device__ int   g_rowptr[NN + 1];
__device__ int   g_cursor[NN];
__device__ int   g_col[EE];
__device__ int   g_root[BG + 1];
__device__ float g_mean[NN * D];
__device__ float g_h1[NN * D];
__device__ float g_h2[NN * D];
__device__ float g_f1[BG * 256];

// ---------------- packed f32x2 helpers ----------------
__device__ __forceinline__ void fma2(unsigned long long& d,
                                     unsigned long long a,
                                     unsigned long long b) {
    asm("fma.rn.f32x2 %0, %1, %2, %0;" : "+l"(d) : "l"(a), "l"(b));
}
__device__ __forceinline__ unsigned long long bcast2(float x) {
    unsigned long long r;
    asm("mov.b64 %0, {%1, %1};" : "=l"(r) : "f"(x));
    return r;
}
__device__ __forceinline__ void unpack2(unsigned long long v, float& lo, float& hi) {
    asm("mov.b64 {%0, %1}, %2;" : "=f"(lo), "=f"(hi) : "l"(v));
}

// ---------------- CSR build ----------------
__global__ void k_init(const int* __restrict__ batch) {
    int i = blockIdx.x * blockDim.x + threadIdx.x;
    if (i < NN) {
        g_deg[i] = 0;
        int b = batch[i];
        if (i == 0 || batch[i - 1] != b) g_root[b] = i;
        if (i == 0) g_root[BG] = NN;
    }
}

__global__ void k_hist(const int* __restrict__ dst) {
    int e = blockIdx.x * blockDim.x + threadIdx.x;
    if (e < EE) atomicAdd(&g_deg[dst[e]], 1);
}

__global__ void k_scan() {
    // single block, 1024 threads, exclusive scan of g_deg -> g_rowptr (+ cursor copy)
    const int C = (NN + 1023) / 1024;  // 49
    __shared__ int part[1024];
    int t = threadIdx.x;
    int base = t * C;
    int s = 0;
    for (int q = 0; q < C; q++) {
        int i = base + q;
        if (i < NN) s += g_deg[i];
    }
    part[t] = s;
    __syncthreads();
    for (int off = 1; off < 1024; off <<= 1) {
        int add = (t >= off) ? part[t - off] : 0;
        __syncthreads();
        part[t] += add;
        __syncthreads();
    }
    int excl = (t == 0) ? 0 : part[t - 1];
    for (int q = 0; q < C; q++) {
        int i = base + q;
        if (i < NN) {
            int d = g_deg[i];
            g_rowptr[i] = excl;
            g_cursor[i] = excl;
            excl += d;
        }
    }
    if (t == 1023) g_rowptr[NN] = part[1023];
}

__global__ void k_fill(const int* __restrict__ src, const int* __restrict__ dst) {
    int e = blockIdx.x * blockDim.x + threadIdx.x;
    if (e < EE) {
        int d = dst[e];
        int p = atomicAdd(&g_cursor[d], 1);
        g_col[p] = src[e];
    }
}

// ---------------- mean aggregation: warp per node, lane = one float4 ----------------
__global__ void k_aggregate(const float* __restrict__ feat, float* __restrict__ mean) {
    int warp = (blockIdx.x * blockDim.x + threadIdx.x) >> 5;
    int lane = threadIdx.x & 31;
    if (warp >= NN) return;
    int s = g_rowptr[warp];
    int e = g_rowptr[warp + 1];
    float4 acc = make_float4(0.f, 0.f, 0.f, 0.f);
    const float4* f4 = (const float4*)feat;
    for (int i = s; i < e; i++) {
        int c = __ldg(&g_col[i]);
        float4 v = __ldg(&f4[c * 32 + lane]);
        acc.x += v.x; acc.y += v.y; acc.z += v.z; acc.w += v.w;
    }
    int cnt = e - s;
    float inv = 1.0f / (float)(cnt > 0 ? cnt : 1);
    acc.x *= inv; acc.y *= inv; acc.z *= inv; acc.w *= inv;
    ((float4*)mean)[warp * 32 + lane] = acc;
}

// ---------------- SAGE GEMM: out = relu(mean@Wl + feat@Wr + bl) ----------------
// M-tile 128, N=128 (full), K-tile 64. 256 threads: jt(16) x nt(16).
// A staged in smem as DUPLICATED f32 pairs {v,v} (8B each, row stride 66 pairs)
// so the inner loop is LDS.64 -> fma.rn.f32x2 with no broadcast movs.
#define APITCH 66
#define GEMM_SMEM (128 * APITCH * 8 + 64 * 128 * 4)  // 67584 + 32768 = 100352

__global__ __launch_bounds__(256, 2)
void k_gemm_sage(const float* __restrict__ Amean, const float* __restrict__ Afeat,
                 const float* __restrict__ Wl, const float* __restrict__ Wr,
                 const float* __restrict__ bias, float* __restrict__ out) {
    extern __shared__ char smemraw[];
    unsigned long long* sA2 = (unsigned long long*)smemraw;        // [128][66] dup pairs
    float4* sW = (float4*)(smemraw + 128 * APITCH * 8);            // [64][32] float4

    const int tid = threadIdx.x;
    const int jt = tid & 15;
    const int nt = tid >> 4;
    const int row0 = blockIdx.x * 128;

    unsigned long long acc[8][4];
#pragma unroll
    for (int i = 0; i < 8; i++)
#pragma unroll
        for (int j = 0; j < 4; j++) acc[i][j] = 0ull;

    for (int t = 0; t < 4; t++) {
        const float* A = (t < 2) ? Amean : Afeat;
        const float* W = (t < 2) ? Wl : Wr;
        const int kb = (t & 1) * 64;

        // load W tile (64x128 floats = 2048 float4)
        {
            const float4* Wg = (const float4*)W + kb * 32;
#pragma unroll
            for (int q = 0; q < 8; q++) {
                int lin = tid + q * 256;
                sW[lin] = Wg[lin];
            }
        }
        // load A tile (128 rows x 64 k), duplicated pairs. row = tid>>1, half = tid&1.
        {
            int r = tid >> 1;
            int kh = (tid & 1) * 32;
            int grow = row0 + r;
            const float4* Ag = (const float4*)(A + (size_t)grow * D + kb + kh);
            unsigned long long* dst = sA2 + r * APITCH + kh;
#pragma unroll
            for (int q = 0; q < 8; q++) {
                float4 v = make_float4(0.f, 0.f, 0.f, 0.f);
                if (grow < NN) v = Ag[q];
                ulonglong2 p01, p23;
                p01.x = bcast2(v.x); p01.y = bcast2(v.y);
                p23.x = bcast2(v.z); p23.y = bcast2(v.w);
                *(ulonglong2*)(dst + q * 4)     = p01;
                *(ulonglong2*)(dst + q * 4 + 2) = p23;
            }
        }
        __syncthreads();

        const ulonglong2* sWu = (const ulonglong2*)sW;
#pragma unroll 8
        for (int k = 0; k < 64; k++) {
            ulonglong2 p0 = sWu[k * 32 + jt * 2];
            ulonglong2 p1 = sWu[k * 32 + jt * 2 + 1];
#pragma unroll
            for (int i = 0; i < 8; i++) {
                unsigned long long aa = sA2[(nt + 16 * i) * APITCH + k];
                fma2(acc[i][0], aa, p0.x);
                fma2(acc[i][1], aa, p0.y);
                fma2(acc[i][2], aa, p1.x);
                fma2(acc[i][3], aa, p1.y);
            }
        }
        __syncthreads();
    }

    float b[8];
#pragma unroll
    for (int c = 0; c < 8; c++) b[c] = bias[jt * 8 + c];

#pragma unroll
    for (int i = 0; i < 8; i++) {
        int row = row0 + nt + 16 * i;
        if (row < NN) {
            float lo[4], hi[4];
#pragma unroll
            for (int j = 0; j < 4; j++) {
                unpack2(acc[i][j], lo[j], hi[j]);
                lo[j] = fmaxf(lo[j] + b[j * 2], 0.f);
                hi[j] = fmaxf(hi[j] + b[j * 2 + 1], 0.f);
            }
            float4* o = (float4*)(out + (size_t)row * D + jt * 8);
            o[0] = make_float4(lo[0], hi[0], lo[1], hi[1]);
            o[1] = make_float4(lo[2], hi[2], lo[3], hi[3]);
        }
    }
}

// ---------------- fused max-pool + MLP 128->256 ----------------
__global__ void k_pool_mlp1(const float* __restrict__ h,
                            const float* __restrict__ W, const float* __restrict__ b) {
    __shared__ float pool[128];
    __shared__ float pmax[256];
    int g = blockIdx.x;
    int tid = threadIdx.x;  // 0..255
    int col = tid & 127, half = tid >> 7;
    int s = g_root[g], e = g_root[g + 1];
    float m = -3.4e38f;
    for (int n = s + half; n < e; n += 2) m = fmaxf(m, h[(size_t)n * D + col]);
    pmax[tid] = m;
    __syncthreads();
    if (tid < 128) pool[tid] = fmaxf(pmax[tid], pmax[tid + 128]);
    __syncthreads();
    float sacc = b[tid];
#pragma unroll 16
    for (int k = 0; k < 128; k++) sacc += pool[k] * W[k * 256 + tid];
    g_f1[g * 256 + tid] = fmaxf(sacc, 0.f);
}

// ---------------- fused MLP 256->128 + head (h_sm, news, concat, sigmoid) ----------------
__global__ void k_mlp2_final(const float* __restrict__ x,
                             const float* __restrict__ W2, const float* __restrict__ b2,
                             const float* __restrict__ Wsm, const float* __restrict__ bsm,
                             const float* __restrict__ Wnews, const float* __restrict__ bnews,
                             const float* __restrict__ Wcat, const float* __restrict__ bcat,
                             float* __restrict__ out) {
    __shared__ float xr[256];
    __shared__ float f2s[128];
    __shared__ float xroot[128];
    int g = blockIdx.x;
    int tid = threadIdx.x;  // 0..127
    xr[tid]       = g_f1[g * 256 + tid];
    xr[tid + 128] = g_f1[g * 256 + 128 + tid];
    xroot[tid] = x[(size_t)g_root[g] * D + tid];
    __syncthreads();
    float s = b2[tid];
#pragma unroll 16
    for (int k = 0; k < 256; k++) s += xr[k] * W2[k * 128 + tid];
    f2s[tid] = fmaxf(s, 0.f);
    __syncthreads();
    if (tid < 32) {
        int kb = tid * 4;
        float s0 = 0.f, s1 = 0.f, n0 = 0.f, n1 = 0.f;
#pragma unroll
        for (int t = 0; t < 4; t++) {
            float fv = f2s[kb + t];
            float xv = xroot[kb + t];
            s0 += fv * Wsm[(kb + t) * 2 + 0];
            s1 += fv * Wsm[(kb + t) * 2 + 1];
            n0 += xv * Wnews[(kb + t) * 2 + 0];
            n1 += xv * Wnews[(kb + t) * 2 + 1];
        }
#pragma unroll
        for (int off = 16; off > 0; off >>= 1) {
            s0 += __shfl_down_sync(0xffffffffu, s0, off);
            s1 += __shfl_down_sync(0xffffffffu, s1, off);
            n0 += __shfl_down_sync(0xffffffffu, n0, off);
            n1 += __shfl_down_sync(0xffffffffu, n1, off);
        }
        if (tid == 0) {
            float h0 = fmaxf(s0 + bsm[0], 0.f);
            float h1 = fmaxf(s1 + bsm[1], 0.f);
            float m0 = fmaxf(n0 + bnews[0], 0.f);
            float m1 = fmaxf(n1 + bnews[1], 0.f);
            float z = h0 * Wcat[0] + h1 * Wcat[1] + m0 * Wcat[2] + m1 * Wcat[3] + bcat[0];
            out[g] = 1.0f / (1.0f + expf(-z));
        }
    }
}

// ---------------- launch ----------------
extern "C" void kernel_launch(void* const* d_in, const int* in_sizes, int n_in,
                              void* d_out, int out_size) {
    const float* x     = (const float*)d_in[0];
    const int*   ei    = (const int*)d_in[1];
    const int*   src   = ei;
    const int*   dst   = ei + EE;
    const int*   batch = (const int*)d_in[2];
    const float* Wl1 = (const float*)d_in[3];
    const float* Wr1 = (const float*)d_in[4];
    const float* bl1 = (const float*)d_in[5];
    const float* Wl2 = (const float*)d_in[6];
    const float* Wr2 = (const float*)d_in[7];
    const float* bl2 = (const float*)d_in[8];
    const float* Wl3 = (const float*)d_in[9];
    const float* Wr3 = (const float*)d_in[10];
    const float* bl3 = (const float*)d_in[11];
    const float* W_f1 = (const float*)d_in[12];
    const float* b_f1 = (const float*)d_in[13];
    const float* W_f2 = (const float*)d_in[14];
    const float* b_f2 = (const float*)d_in[15];
    const float* W_sm = (const float*)d_in[16];
    const float* b_sm = (const float*)d_in[17];
    const float* W_news = (const float*)d_in[18];
    const float* b_news = (const float*)d_in[19];
    const float* W_cat = (const float*)d_in[20];
    const float* b_cat = (const float*)d_in[21];
    float* out = (float*)d_out;

    float *mean, *h1, *h2;
    cudaGetSymbolAddress((void**)&mean, g_mean);
    cudaGetSymbolAddress((void**)&h1, g_h1);
    cudaGetSymbolAddress((void**)&h2, g_h2);

    const int TB = 256;
    const int gN = (NN + TB - 1) / TB;
    const int gE = (EE + TB - 1) / TB;

    // CSR build (reused by all 3 layers) + per-graph roots
    k_init<<<gN, TB>>>(batch);
    k_hist<<<gE, TB>>>(dst);
    k_scan<<<1, 1024>>>();
    k_fill<<<gE, TB>>>(src, dst);

    const int gAgg = (NN * 32 + TB - 1) / TB;  // warp per node
    const int gGemm = (NN + 127) / 128;        // 391
    cudaFuncSetAttribute(k_gemm_sage, cudaFuncAttributeMaxDynamicSharedMemorySize,
                         GEMM_SMEM);

    // layer 1: x -> h1
    k_aggregate<<<gAgg, TB>>>(x, mean);
    k_gemm_sage<<<gGemm, TB, GEMM_SMEM>>>(mean, x, Wl1, Wr1, bl1, h1);
    // layer 2: h1 -> h2
    k_aggregate<<<gAgg, TB>>>(h1, mean);
    k_gemm_sage<<<gGemm, TB, GEMM_SMEM>>>(mean, h1, Wl2, Wr2, bl2, h2);
    // layer 3: h2 -> h1
    k_aggregate<<<gAgg, TB>>>(h2, mean);
    k_gemm_sage<<<gGemm, TB, GEMM_SMEM>>>(mean, h2, Wl3, Wr3, bl3, h1);

    // pooled head (fused)
    k_pool_mlp1<<<BG, 256>>>(h1, W_f1, b_f1);
    k_mlp2_final<<<BG, 128>>>(x, W_f2, b_f2, W_sm, b_sm, W_news, b_news,
                              W_cat, b_cat, out);
}

// round 8
// speedup vs baseline: 1.4915x; 1.4915x over previous
#include <cuda_runtime.h>
#include <cuda_bf16.h>
#include <math.h>
#include <stdint.h>

#define NN 50000
#define EE 800000
#define BG 512
#define D  128

// ---------------- scratch (static device globals; no allocation) ----------------
__device__ int   g_deg[NN];
__device__ int   g_rowptr[NN + 1];
__device__ int   g_cursor[NN];
__device__ int   g_col[EE];
__device__ int   g_root[BG + 1];
__device__ float g_mean[NN * D];
__device__ float g_h1[NN * D];
__device__ float g_h2[NN * D];
__device__ float g_f1[BG * 256];
// W in per-thread mma-fragment layout: [layer][k_step 16][n_atom 16][lane 32]
// each uint4 = {bh0, bh1, bl0, bl1}
__device__ uint4 g_Wfrag[3 * 16 * 16 * 32];

// ---------------- CSR build ----------------
__global__ void k_init(const int* __restrict__ batch) {
    int i = blockIdx.x * blockDim.x + threadIdx.x;
    if (i < NN) {
        g_deg[i] = 0;
        int b = batch[i];
        if (i == 0 || batch[i - 1] != b) g_root[b] = i;
        if (i == 0) g_root[BG] = NN;
    }
}

__global__ void k_hist(const int* __restrict__ dst) {
    int e = blockIdx.x * blockDim.x + threadIdx.x;
    if (e < EE) atomicAdd(&g_deg[dst[e]], 1);
}

__global__ void k_scan() {
    const int C = (NN + 1023) / 1024;  // 49
    __shared__ int part[1024];
    int t = threadIdx.x;
    int base = t * C;
    int s = 0;
    for (int q = 0; q < C; q++) {
        int i = base + q;
        if (i < NN) s += g_deg[i];
    }
    part[t] = s;
    __syncthreads();
    for (int off = 1; off < 1024; off <<= 1) {
        int add = (t >= off) ? part[t - off] : 0;
        __syncthreads();
        part[t] += add;
        __syncthreads();
    }
    int excl = (t == 0) ? 0 : part[t - 1];
    for (int q = 0; q < C; q++) {
        int i = base + q;
        if (i < NN) {
            int d = g_deg[i];
            g_rowptr[i] = excl;
            g_cursor[i] = excl;
            excl += d;
        }
    }
    if (t == 1023) g_rowptr[NN] = part[1023];
}

__global__ void k_fill(const int* __restrict__ src, const int* __restrict__ dst) {
    int e = blockIdx.x * blockDim.x + threadIdx.x;
    if (e < EE) {
        int d = dst[e];
        int p = atomicAdd(&g_cursor[d], 1);
        g_col[p] = src[e];
    }
}

// ---------------- weight prep: fp32 [Wl;Wr] -> bf16 hi/lo mma B-fragments ----------------
// B fragment for mma.m16n8k16 (row.col): lane ln holds
//   b0 = {B[k0 + (ln&3)*2][n0 + (ln>>2)], B[k0 + (ln&3)*2 + 1][same n]}
//   b1 = same with k += 8
__global__ void k_prepW(const float* __restrict__ Wl1, const float* __restrict__ Wr1,
                        const float* __restrict__ Wl2, const float* __restrict__ Wr2,
                        const float* __restrict__ Wl3, const float* __restrict__ Wr3) {
    int idx = blockIdx.x * blockDim.x + threadIdx.x;  // 3*16*16*32 = 24576
    if (idx >= 3 * 16 * 16 * 32) return;
    int L    = idx >> 13;
    int rem  = idx & 8191;
    int t    = rem >> 9;          // k_step 0..15
    int na   = (rem >> 5) & 15;   // n_atom 0..15
    int lane = rem & 31;
    const float* Wl = (L == 0) ? Wl1 : (L == 1) ? Wl2 : Wl3;
    const float* Wr = (L == 0) ? Wr1 : (L == 1) ? Wr2 : Wr3;
    int n  = na * 8 + (lane >> 2);
    int k0 = t * 16 + (lane & 3) * 2;

    float w[4];
#pragma unroll
    for (int q = 0; q < 4; q++) {
        int k = k0 + (q >> 1) * 8 + (q & 1);  // k0, k0+1, k0+8, k0+9
        w[q] = (k < 128) ? Wl[k * 128 + n] : Wr[(k - 128) * 128 + n];
    }
    unsigned short h[4], l[4];
#pragma unroll
    for (int q = 0; q < 4; q++) {
        __nv_bfloat16 hb = __float2bfloat16(w[q]);
        __nv_bfloat16 lb = __float2bfloat16(w[q] - __bfloat162float(hb));
        h[q] = __bfloat16_as_ushort(hb);
        l[q] = __bfloat16_as_ushort(lb);
    }
    uint4 v;
    v.x = (uint32_t)h[0] | ((uint32_t)h[1] << 16);  // bh0
    v.y = (uint32_t)h[2] | ((uint32_t)h[3] << 16);  // bh1
    v.z = (uint32_t)l[0] | ((uint32_t)l[1] << 16);  // bl0
    v.w = (uint32_t)l[2] | ((uint32_t)l[3] << 16);  // bl1
    g_Wfrag[idx] = v;
}

// ---------------- mean aggregation: warp per node, lane = one float4 ----------------
__global__ void k_aggregate(const float* __restrict__ feat, float* __restrict__ mean) {
    int warp = (blockIdx.x * blockDim.x + threadIdx.x) >> 5;
    int lane = threadIdx.x & 31;
    if (warp >= NN) return;
    int s = g_rowptr[warp];
    int e = g_rowptr[warp + 1];
    float4 acc = make_float4(0.f, 0.f, 0.f, 0.f);
    const float4* f4 = (const float4*)feat;
    for (int i = s; i < e; i++) {
        int c = __ldg(&g_col[i]);
        float4 v = __ldg(&f4[c * 32 + lane]);
        acc.x += v.x; acc.y += v.y; acc.z += v.z; acc.w += v.w;
    }
    int cnt = e - s;
    float inv = 1.0f / (float)(cnt > 0 ? cnt : 1);
    acc.x *= inv; acc.y *= inv; acc.z *= inv; acc.w *= inv;
    ((float4*)mean)[warp * 32 + lane] = acc;
}

// ---------------- tensor-core SAGE GEMM ----------------
// out[128 rows tile][128] = relu([mean|feat] @ W + bias), K = 256.
// 3-term bf16 split: D = Ah*Bh + Ah*Bl + Al*Bh (fp32 accumulate).
// 8 warps: warp_row (2) x warp_col (4); warp tile 64x32.
// A staged per 64-K chunk in smem bf16 hi/lo, pitch 36 words (conflict-free frag loads).
#define APITCH 36

__device__ __forceinline__ void mma_bf16(float* c, const uint32_t* a,
                                         uint32_t b0, uint32_t b1) {
    asm("mma.sync.aligned.m16n8k16.row.col.f32.bf16.bf16.f32 "
        "{%0,%1,%2,%3}, {%4,%5,%6,%7}, {%8,%9}, {%0,%1,%2,%3};"
        : "+f"(c[0]), "+f"(c[1]), "+f"(c[2]), "+f"(c[3])
        : "r"(a[0]), "r"(a[1]), "r"(a[2]), "r"(a[3]), "r"(b0), "r"(b1));
}

__global__ __launch_bounds__(256)
void k_gemm_mma(const float* __restrict__ Amean, const float* __restrict__ Afeat,
                const uint4* __restrict__ Wfrag, const float* __restrict__ bias,
                float* __restrict__ out) {
    __shared__ uint32_t sAhi[128 * APITCH];
    __shared__ uint32_t sAlo[128 * APITCH];

    const int tid  = threadIdx.x;
    const int wid  = tid >> 5;
    const int lane = tid & 31;
    const int wr = wid >> 2;           // 0..1
    const int wc = wid & 3;            // 0..3
    const int row0 = blockIdx.x * 128;

    float acc[4][4][4];
#pragma unroll
    for (int i = 0; i < 4; i++)
#pragma unroll
        for (int j = 0; j < 4; j++)
#pragma unroll
            for (int r = 0; r < 4; r++) acc[i][j][r] = 0.f;

    for (int chunk = 0; chunk < 4; chunk++) {
        const float* A = (chunk < 2) ? Amean : Afeat;
        const int kb = (chunk & 1) * 64;

        // ---- stage A chunk: 128 rows x 64 k -> bf16 hi/lo smem images ----
        {
            int r = tid >> 1;
            int half = tid & 1;
            int grow = row0 + r;
            const float4* Ag = (const float4*)(A + (size_t)grow * D + kb);
#pragma unroll
            for (int q = 0; q < 8; q++) {
                float4 v = make_float4(0.f, 0.f, 0.f, 0.f);
                if (grow < NN) v = __ldg(&Ag[half * 8 + q]);
                __nv_bfloat16 hx = __float2bfloat16(v.x);
                __nv_bfloat16 hy = __float2bfloat16(v.y);
                __nv_bfloat16 hz = __float2bfloat16(v.z);
                __nv_bfloat16 hw = __float2bfloat16(v.w);
                uint2 hv, lv;
                hv.x = (uint32_t)__bfloat16_as_ushort(hx) |
                       ((uint32_t)__bfloat16_as_ushort(hy) << 16);
                hv.y = (uint32_t)__bfloat16_as_ushort(hz) |
                       ((uint32_t)__bfloat16_as_ushort(hw) << 16);
                __nv_bfloat16 lx = __float2bfloat16(v.x - __bfloat162float(hx));
                __nv_bfloat16 ly = __float2bfloat16(v.y - __bfloat162float(hy));
                __nv_bfloat16 lz = __float2bfloat16(v.z - __bfloat162float(hz));
                __nv_bfloat16 lw = __float2bfloat16(v.w - __bfloat162float(hw));
                lv.x = (uint32_t)__bfloat16_as_ushort(lx) |
                       ((uint32_t)__bfloat16_as_ushort(ly) << 16);
                lv.y = (uint32_t)__bfloat16_as_ushort(lz) |
                       ((uint32_t)__bfloat16_as_ushort(lw) << 16);
                int c = half * 16 + q * 2;
                *(uint2*)&sAhi[r * APITCH + c] = hv;
                *(uint2*)&sAlo[r * APITCH + c] = lv;
            }
        }
        __syncthreads();

        // ---- mma over 4 k-steps of 16 ----
#pragma unroll
        for (int t = 0; t < 4; t++) {
            uint4 B[4];
#pragma unroll
            for (int j = 0; j < 4; j++)
                B[j] = __ldg(&Wfrag[(((chunk * 4 + t) * 16) + (wc * 4 + j)) * 32 + lane]);

            const int rb = wr * 64 + (lane >> 2);
            const int cw = t * 8 + (lane & 3);
#pragma unroll
            for (int i = 0; i < 4; i++) {
                int base = (rb + i * 16) * APITCH;
                uint32_t ah[4], al[4];
                ah[0] = sAhi[base + cw];
                ah[1] = sAhi[base + 8 * APITCH + cw];
                ah[2] = sAhi[base + cw + 4];
                ah[3] = sAhi[base + 8 * APITCH + cw + 4];
                al[0] = sAlo[base + cw];
                al[1] = sAlo[base + 8 * APITCH + cw];
                al[2] = sAlo[base + cw + 4];
                al[3] = sAlo[base + 8 * APITCH + cw + 4];
#pragma unroll
                for (int j = 0; j < 4; j++) {
                    mma_bf16(acc[i][j], ah, B[j].x, B[j].y);  // Ah*Bh
                    mma_bf16(acc[i][j], ah, B[j].z, B[j].w);  // Ah*Bl
                    mma_bf16(acc[i][j], al, B[j].x, B[j].y);  // Al*Bh
                }
            }
        }
        __syncthreads();
    }

    // ---- epilogue: bias + relu, float2 stores ----
#pragma unroll
    for (int j = 0; j < 4; j++) {
        int col = wc * 32 + j * 8 + (lane & 3) * 2;
        float b0 = __ldg(&bias[col]);
        float b1 = __ldg(&bias[col + 1]);
#pragma unroll
        for (int i = 0; i < 4; i++) {
            int row = row0 + wr * 64 + i * 16 + (lane >> 2);
            if (row < NN) {
                float2 v0;
                v0.x = fmaxf(acc[i][j][0] + b0, 0.f);
                v0.y = fmaxf(acc[i][j][1] + b1, 0.f);
                *(float2*)(out + (size_t)row * D + col) = v0;
            }
            if (row + 8 < NN) {
                float2 v1;
                v1.x = fmaxf(acc[i][j][2] + b0, 0.f);
                v1.y = fmaxf(acc[i][j][3] + b1, 0.f);
                *(float2*)(out + (size_t)(row + 8) * D + col) = v1;
            }
        }
    }
}

// ---------------- fused max-pool + MLP 128->256 ----------------
__global__ void k_pool_mlp1(const float* __restrict__ h,
                            const float* __restrict__ W, const float* __restrict__ b) {
    __shared__ float pool[128];
    __shared__ float pmax[256];
    int g = blockIdx.x;
    int tid = threadIdx.x;  // 0..255
    int col = tid & 127, half = tid >> 7;
    int s = g_root[g], e = g_root[g + 1];
    float m = -3.4e38f;
    for (int n = s + half; n < e; n += 2) m = fmaxf(m, h[(size_t)n * D + col]);
    pmax[tid] = m;
    __syncthreads();
    if (tid < 128) pool[tid] = fmaxf(pmax[tid], pmax[tid + 128]);
    __syncthreads();
    float sacc = b[tid];
#pragma unroll 16
    for (int k = 0; k < 128; k++) sacc += pool[k] * W[k * 256 + tid];
    g_f1[g * 256 + tid] = fmaxf(sacc, 0.f);
}

// ---------------- fused MLP 256->128 + head (h_sm, news, concat, sigmoid) ----------------
__global__ void k_mlp2_final(const float* __restrict__ x,
                             const float* __restrict__ W2, const float* __restrict__ b2,
                             const float* __restrict__ Wsm, const float* __restrict__ bsm,
                             const float* __restrict__ Wnews, const float* __restrict__ bnews,
                             const float* __restrict__ Wcat, const float* __restrict__ bcat,
                             float* __restrict__ out) {
    __shared__ float xr[256];
    __shared__ float f2s[128];
    __shared__ float xroot[128];
    int g = blockIdx.x;
    int tid = threadIdx.x;  // 0..127
    xr[tid]       = g_f1[g * 256 + tid];
    xr[tid + 128] = g_f1[g * 256 + 128 + tid];
    xroot[tid] = x[(size_t)g_root[g] * D + tid];
    __syncthreads();
    float s = b2[tid];
#pragma unroll 16
    for (int k = 0; k < 256; k++) s += xr[k] * W2[k * 128 + tid];
    f2s[tid] = fmaxf(s, 0.f);
    __syncthreads();
    if (tid < 32) {
        int kb = tid * 4;
        float s0 = 0.f, s1 = 0.f, n0 = 0.f, n1 = 0.f;
#pragma unroll
        for (int t = 0; t < 4; t++) {
            float fv = f2s[kb + t];
            float xv = xroot[kb + t];
            s0 += fv * Wsm[(kb + t) * 2 + 0];
            s1 += fv * Wsm[(kb + t) * 2 + 1];
            n0 += xv * Wnews[(kb + t) * 2 + 0];
            n1 += xv * Wnews[(kb + t) * 2 + 1];
        }
#pragma unroll
        for (int off = 16; off > 0; off >>= 1) {
            s0 += __shfl_down_sync(0xffffffffu, s0, off);
            s1 += __shfl_down_sync(0xffffffffu, s1, off);
            n0 += __shfl_down_sync(0xffffffffu, n0, off);
            n1 += __shfl_down_sync(0xffffffffu, n1, off);
        }
        if (tid == 0) {
            float h0 = fmaxf(s0 + bsm[0], 0.f);
            float h1 = fmaxf(s1 + bsm[1], 0.f);
            float m0 = fmaxf(n0 + bnews[0], 0.f);
            float m1 = fmaxf(n1 + bnews[1], 0.f);
            float z = h0 * Wcat[0] + h1 * Wcat[1] + m0 * Wcat[2] + m1 * Wcat[3] + bcat[0];
            out[g] = 1.0f / (1.0f + expf(-z));
        }
    }
}

// ---------------- launch ----------------
extern "C" void kernel_launch(void* const* d_in, const int* in_sizes, int n_in,
                              void* d_out, int out_size) {
    const float* x     = (const float*)d_in[0];
    const int*   ei    = (const int*)d_in[1];
    const int*   src   = ei;
    const int*   dst   = ei + EE;
    const int*   batch = (const int*)d_in[2];
    const float* Wl1 = (const float*)d_in[3];
    const float* Wr1 = (const float*)d_in[4];
    const float* bl1 = (const float*)d_in[5];
    const float* Wl2 = (const float*)d_in[6];
    const float* Wr2 = (const float*)d_in[7];
    const float* bl2 = (const float*)d_in[8];
    const float* Wl3 = (const float*)d_in[9];
    const float* Wr3 = (const float*)d_in[10];
    const float* bl3 = (const float*)d_in[11];
    const float* W_f1 = (const float*)d_in[12];
    const float* b_f1 = (const float*)d_in[13];
    const float* W_f2 = (const float*)d_in[14];
    const float* b_f2 = (const float*)d_in[15];
    const float* W_sm = (const float*)d_in[16];
    const float* b_sm = (const float*)d_in[17];
    const float* W_news = (const float*)d_in[18];
    const float* b_news = (const float*)d_in[19];
    const float* W_cat = (const float*)d_in[20];
    const float* b_cat = (const float*)d_in[21];
    float* out = (float*)d_out;

    float *mean, *h1, *h2;
    uint4* wfrag;
    cudaGetSymbolAddress((void**)&mean, g_mean);
    cudaGetSymbolAddress((void**)&h1, g_h1);
    cudaGetSymbolAddress((void**)&h2, g_h2);
    cudaGetSymbolAddress((void**)&wfrag, g_Wfrag);

    const int TB = 256;
    const int gN = (NN + TB - 1) / TB;
    const int gE = (EE + TB - 1) / TB;

    // CSR build + roots + weight fragment prep
    k_init<<<gN, TB>>>(batch);
    k_prepW<<<(3 * 16 * 16 * 32 + TB - 1) / TB, TB>>>(Wl1, Wr1, Wl2, Wr2, Wl3, Wr3);
    k_hist<<<gE, TB>>>(dst);
    k_scan<<<1, 1024>>>();
    k_fill<<<gE, TB>>>(src, dst);

    const int gAgg = (NN * 32 + TB - 1) / TB;  // warp per node
    const int gGemm = (NN + 127) / 128;        // 391

    // layer 1: x -> h1
    k_aggregate<<<gAgg, TB>>>(x, mean);
    k_gemm_mma<<<gGemm, TB>>>(mean, x, wfrag, bl1, h1);
    // layer 2: h1 -> h2
    k_aggregate<<<gAgg, TB>>>(h1, mean);
    k_gemm_mma<<<gGemm, TB>>>(mean, h1, wfrag + 8192, bl2, h2);
    // layer 3: h2 -> h1
    k_aggregate<<<gAgg, TB>>>(h2, mean);
    k_gemm_mma<<<gGemm, TB>>>(mean, h2, wfrag + 16384, bl3, h1);

    // pooled head (fused)
    k_pool_mlp1<<<BG, 256>>>(h1, W_f1, b_f1);
    k_mlp2_final<<<BG, 128>>>(x, W_f2, b_f2, W_sm, b_sm, W_news, b_news,
                              W_cat, b_cat, out);
}

// round 9
// speedup vs baseline: 1.8454x; 1.2372x over previous
#include <cuda_runtime.h>
#include <cuda_bf16.h>
#include <math.h>
#include <stdint.h>

#define NN 50000
#define EE 800000
#define BG 512
#define D  128
#define SCAN_BLKS 49   // ceil(50000 / 1024)

// ---------------- scratch (static device globals; no allocation) ----------------
__device__ int   g_deg[NN];
__device__ int   g_rowptr[NN + 1];
__device__ int   g_cursor[NN];
__device__ int   g_col[EE];
__device__ int   g_root[BG + 1];
__device__ int   g_bsum[SCAN_BLKS];
__device__ int   g_boff[SCAN_BLKS];
__device__ float g_mean[NN * D];
__device__ float g_h1[NN * D];
__device__ float g_h2[NN * D];
__device__ float g_f1[BG * 256];
// W in per-thread mma-fragment layout: [layer][k_step 16][n_atom 16][lane 32]
// each uint4 = {bh0, bh1, bl0, bl1}
__device__ uint4 g_Wfrag[3 * 16 * 16 * 32];

// ---------------- CSR build ----------------
__global__ void k_init(const int* __restrict__ batch) {
    int i = blockIdx.x * blockDim.x + threadIdx.x;
    if (i < NN) {
        g_deg[i] = 0;
        int b = batch[i];
        if (i == 0 || batch[i - 1] != b) g_root[b] = i;
        if (i == 0) g_root[BG] = NN;
    }
}

__global__ void k_hist(const int* __restrict__ dst) {
    int e = blockIdx.x * blockDim.x + threadIdx.x;
    if (e < EE) atomicAdd(&g_deg[dst[e]], 1);
}

// phase 1: per-block inclusive scan -> exclusive values (no block offset) + block sums
__global__ void k_scan_blk() {
    __shared__ int sc[1024];
    int t = threadIdx.x;
    int i = blockIdx.x * 1024 + t;
    int d = (i < NN) ? g_deg[i] : 0;
    sc[t] = d;
    __syncthreads();
#pragma unroll
    for (int off = 1; off < 1024; off <<= 1) {
        int add = (t >= off) ? sc[t - off] : 0;
        __syncthreads();
        sc[t] += add;
        __syncthreads();
    }
    if (i < NN) g_rowptr[i] = sc[t] - d;     // exclusive within block
    if (t == 1023) g_bsum[blockIdx.x] = sc[1023];
}

// phase 2: scan the block sums (tiny, 1 warp pass)
__global__ void k_scan_top() {
    __shared__ int sc[64];
    int t = threadIdx.x;  // 0..63
    int v = (t < SCAN_BLKS) ? g_bsum[t] : 0;
    sc[t] = v;
    __syncthreads();
#pragma unroll
    for (int off = 1; off < 64; off <<= 1) {
        int add = (t >= off) ? sc[t - off] : 0;
        __syncthreads();
        sc[t] += add;
        __syncthreads();
    }
    if (t < SCAN_BLKS) g_boff[t] = sc[t] - v;  // exclusive
    if (t == SCAN_BLKS - 1) g_rowptr[NN] = sc[t];
}

// phase 3: add block offsets, emit rowptr + cursor
__global__ void k_scan_add() {
    int t = threadIdx.x;
    int i = blockIdx.x * 1024 + t;
    if (i < NN) {
        int v = g_rowptr[i] + g_boff[blockIdx.x];
        g_rowptr[i] = v;
        g_cursor[i] = v;
    }
}

__global__ void k_fill(const int* __restrict__ src, const int* __restrict__ dst) {
    int e = blockIdx.x * blockDim.x + threadIdx.x;
    if (e < EE) {
        int d = dst[e];
        int p = atomicAdd(&g_cursor[d], 1);
        g_col[p] = src[e];
    }
}

// ---------------- weight prep: fp32 [Wl;Wr] -> bf16 hi/lo mma B-fragments ----------------
__global__ void k_prepW(const float* __restrict__ Wl1, const float* __restrict__ Wr1,
                        const float* __restrict__ Wl2, const float* __restrict__ Wr2,
                        const float* __restrict__ Wl3, const float* __restrict__ Wr3) {
    int idx = blockIdx.x * blockDim.x + threadIdx.x;  // 3*16*16*32 = 24576
    if (idx >= 3 * 16 * 16 * 32) return;
    int L    = idx >> 13;
    int rem  = idx & 8191;
    int t    = rem >> 9;          // k_step 0..15
    int na   = (rem >> 5) & 15;   // n_atom 0..15
    int lane = rem & 31;
    const float* Wl = (L == 0) ? Wl1 : (L == 1) ? Wl2 : Wl3;
    const float* Wr = (L == 0) ? Wr1 : (L == 1) ? Wr2 : Wr3;
    int n  = na * 8 + (lane >> 2);
    int k0 = t * 16 + (lane & 3) * 2;

    float w[4];
#pragma unroll
    for (int q = 0; q < 4; q++) {
        int k = k0 + (q >> 1) * 8 + (q & 1);  // k0, k0+1, k0+8, k0+9
        w[q] = (k < 128) ? Wl[k * 128 + n] : Wr[(k - 128) * 128 + n];
    }
    unsigned short h[4], l[4];
#pragma unroll
    for (int q = 0; q < 4; q++) {
        __nv_bfloat16 hb = __float2bfloat16(w[q]);
        __nv_bfloat16 lb = __float2bfloat16(w[q] - __bfloat162float(hb));
        h[q] = __bfloat16_as_ushort(hb);
        l[q] = __bfloat16_as_ushort(lb);
    }
    uint4 v;
    v.x = (uint32_t)h[0] | ((uint32_t)h[1] << 16);  // bh0
    v.y = (uint32_t)h[2] | ((uint32_t)h[3] << 16);  // bh1
    v.z = (uint32_t)l[0] | ((uint32_t)l[1] << 16);  // bl0
    v.w = (uint32_t)l[2] | ((uint32_t)l[3] << 16);  // bl1
    g_Wfrag[idx] = v;
}

// ---------------- mean aggregation: warp per node, lane = one float4 ----------------
__global__ void k_aggregate(const float* __restrict__ feat, float* __restrict__ mean) {
    int warp = (blockIdx.x * blockDim.x + threadIdx.x) >> 5;
    int lane = threadIdx.x & 31;
    if (warp >= NN) return;
    int s = g_rowptr[warp];
    int e = g_rowptr[warp + 1];
    float4 acc = make_float4(0.f, 0.f, 0.f, 0.f);
    const float4* f4 = (const float4*)feat;
    for (int i = s; i < e; i++) {
        int c = __ldg(&g_col[i]);
        float4 v = __ldg(&f4[c * 32 + lane]);
        acc.x += v.x; acc.y += v.y; acc.z += v.z; acc.w += v.w;
    }
    int cnt = e - s;
    float inv = 1.0f / (float)(cnt > 0 ? cnt : 1);
    acc.x *= inv; acc.y *= inv; acc.z *= inv; acc.w *= inv;
    ((float4*)mean)[warp * 32 + lane] = acc;
}

// ---------------- tensor-core SAGE GEMM ----------------
// out[128 rows tile][128] = relu([mean|feat] @ W + bias), K = 256.
// 3-term bf16 split: D = Ah*Bh + Ah*Bl + Al*Bh (fp32 accumulate).
// 8 warps: warp_row (2) x warp_col (4); warp tile 64x32.
// A staged per 64-K chunk in smem bf16 hi/lo, pitch 36 words (conflict-free frag loads).
#define APITCH 36

__device__ __forceinline__ void mma_bf16(float* c, const uint32_t* a,
                                         uint32_t b0, uint32_t b1) {
    asm("mma.sync.aligned.m16n8k16.row.col.f32.bf16.bf16.f32 "
        "{%0,%1,%2,%3}, {%4,%5,%6,%7}, {%8,%9}, {%0,%1,%2,%3};"
        : "+f"(c[0]), "+f"(c[1]), "+f"(c[2]), "+f"(c[3])
        : "r"(a[0]), "r"(a[1]), "r"(a[2]), "r"(a[3]), "r"(b0), "r"(b1));
}

__global__ __launch_bounds__(256)
void k_gemm_mma(const float* __restrict__ Amean, const float* __restrict__ Afeat,
                const uint4* __restrict__ Wfrag, const float* __restrict__ bias,
                float* __restrict__ out) {
    __shared__ uint32_t sAhi[128 * APITCH];
    __shared__ uint32_t sAlo[128 * APITCH];

    const int tid  = threadIdx.x;
    const int wid  = tid >> 5;
    const int lane = tid & 31;
    const int wr = wid >> 2;           // 0..1
    const int wc = wid & 3;            // 0..3
    const int row0 = blockIdx.x * 128;

    float acc[4][4][4];
#pragma unroll
    for (int i = 0; i < 4; i++)
#pragma unroll
        for (int j = 0; j < 4; j++)
#pragma unroll
            for (int r = 0; r < 4; r++) acc[i][j][r] = 0.f;

    for (int chunk = 0; chunk < 4; chunk++) {
        const float* A = (chunk < 2) ? Amean : Afeat;
        const int kb = (chunk & 1) * 64;

        // ---- stage A chunk: 128 rows x 64 k -> bf16 hi/lo smem images ----
        {
            int r = tid >> 1;
            int half = tid & 1;
            int grow = row0 + r;
            const float4* Ag = (const float4*)(A + (size_t)grow * D + kb);
#pragma unroll
            for (int q = 0; q < 8; q++) {
                float4 v = make_float4(0.f, 0.f, 0.f, 0.f);
                if (grow < NN) v = __ldg(&Ag[half * 8 + q]);
                __nv_bfloat16 hx = __float2bfloat16(v.x);
                __nv_bfloat16 hy = __float2bfloat16(v.y);
                __nv_bfloat16 hz = __float2bfloat16(v.z);
                __nv_bfloat16 hw = __float2bfloat16(v.w);
                uint2 hv, lv;
                hv.x = (uint32_t)__bfloat16_as_ushort(hx) |
                       ((uint32_t)__bfloat16_as_ushort(hy) << 16);
                hv.y = (uint32_t)__bfloat16_as_ushort(hz) |
                       ((uint32_t)__bfloat16_as_ushort(hw) << 16);
                __nv_bfloat16 lx = __float2bfloat16(v.x - __bfloat162float(hx));
                __nv_bfloat16 ly = __float2bfloat16(v.y - __bfloat162float(hy));
                __nv_bfloat16 lz = __float2bfloat16(v.z - __bfloat162float(hz));
                __nv_bfloat16 lw = __float2bfloat16(v.w - __bfloat162float(hw));
                lv.x = (uint32_t)__bfloat16_as_ushort(lx) |
                       ((uint32_t)__bfloat16_as_ushort(ly) << 16);
                lv.y = (uint32_t)__bfloat16_as_ushort(lz) |
                       ((uint32_t)__bfloat16_as_ushort(lw) << 16);
                int c = half * 16 + q * 2;
                *(uint2*)&sAhi[r * APITCH + c] = hv;
                *(uint2*)&sAlo[r * APITCH + c] = lv;
            }
        }
        __syncthreads();

        // ---- mma over 4 k-steps of 16 ----
#pragma unroll
        for (int t = 0; t < 4; t++) {
            uint4 B[4];
#pragma unroll
            for (int j = 0; j < 4; j++)
                B[j] = __ldg(&Wfrag[(((chunk * 4 + t) * 16) + (wc * 4 + j)) * 32 + lane]);

            const int rb = wr * 64 + (lane >> 2);
            const int cw = t * 8 + (lane & 3);
#pragma unroll
            for (int i = 0; i < 4; i++) {
                int base = (rb + i * 16) * APITCH;
                uint32_t ah[4], al[4];
                ah[0] = sAhi[base + cw];
                ah[1] = sAhi[base + 8 * APITCH + cw];
                ah[2] = sAhi[base + cw + 4];
                ah[3] = sAhi[base + 8 * APITCH + cw + 4];
                al[0] = sAlo[base + cw];
                al[1] = sAlo[base + 8 * APITCH + cw];
                al[2] = sAlo[base + cw + 4];
                al[3] = sAlo[base + 8 * APITCH + cw + 4];
#pragma unroll
                for (int j = 0; j < 4; j++) {
                    mma_bf16(acc[i][j], ah, B[j].x, B[j].y);  // Ah*Bh
                    mma_bf16(acc[i][j], ah, B[j].z, B[j].w);  // Ah*Bl
                    mma_bf16(acc[i][j], al, B[j].x, B[j].y);  // Al*Bh
                }
            }
        }
        __syncthreads();
    }

    // ---- epilogue: bias + relu, float2 stores ----
#pragma unroll
    for (int j = 0; j < 4; j++) {
        int col = wc * 32 + j * 8 + (lane & 3) * 2;
        float b0 = __ldg(&bias[col]);
        float b1 = __ldg(&bias[col + 1]);
#pragma unroll
        for (int i = 0; i < 4; i++) {
            int row = row0 + wr * 64 + i * 16 + (lane >> 2);
            if (row < NN) {
                float2 v0;
                v0.x = fmaxf(acc[i][j][0] + b0, 0.f);
                v0.y = fmaxf(acc[i][j][1] + b1, 0.f);
                *(float2*)(out + (size_t)row * D + col) = v0;
            }
            if (row + 8 < NN) {
                float2 v1;
                v1.x = fmaxf(acc[i][j][2] + b0, 0.f);
                v1.y = fmaxf(acc[i][j][3] + b1, 0.f);
                *(float2*)(out + (size_t)(row + 8) * D + col) = v1;
            }
        }
    }
}

// ---------------- fused max-pool + MLP 128->256 ----------------
__global__ void k_pool_mlp1(const float* __restrict__ h,
                            const float* __restrict__ W, const float* __restrict__ b) {
    __shared__ float pool[128];
    __shared__ float pmax[256];
    int g = blockIdx.x;
    int tid = threadIdx.x;  // 0..255
    int col = tid & 127, half = tid >> 7;
    int s = g_root[g], e = g_root[g + 1];
    float m = -3.4e38f;
    for (int n = s + half; n < e; n += 2) m = fmaxf(m, h[(size_t)n * D + col]);
    pmax[tid] = m;
    __syncthreads();
    if (tid < 128) pool[tid] = fmaxf(pmax[tid], pmax[tid + 128]);
    __syncthreads();
    float sacc = b[tid];
#pragma unroll 16
    for (int k = 0; k < 128; k++) sacc += pool[k] * W[k * 256 + tid];
    g_f1[g * 256 + tid] = fmaxf(sacc, 0.f);
}

// ---------------- fused MLP 256->128 + head (h_sm, news, concat, sigmoid) ----------------
__global__ void k_mlp2_final(const float* __restrict__ x,
                             const float* __restrict__ W2, const float* __restrict__ b2,
                             const float* __restrict__ Wsm, const float* __restrict__ bsm,
                             const float* __restrict__ Wnews, const float* __restrict__ bnews,
                             const float* __restrict__ Wcat, const float* __restrict__ bcat,
                             float* __restrict__ out) {
    __shared__ float xr[256];
    __shared__ float f2s[128];
    __shared__ float xroot[128];
    int g = blockIdx.x;
    int tid = threadIdx.x;  // 0..127
    xr[tid]       = g_f1[g * 256 + tid];
    xr[tid + 128] = g_f1[g * 256 + 128 + tid];
    xroot[tid] = x[(size_t)g_root[g] * D + tid];
    __syncthreads();
    float s = b2[tid];
#pragma unroll 16
    for (int k = 0; k < 256; k++) s += xr[k] * W2[k * 128 + tid];
    f2s[tid] = fmaxf(s, 0.f);
    __syncthreads();
    if (tid < 32) {
        int kb = tid * 4;
        float s0 = 0.f, s1 = 0.f, n0 = 0.f, n1 = 0.f;
#pragma unroll
        for (int t = 0; t < 4; t++) {
            float fv = f2s[kb + t];
            float xv = xroot[kb + t];
            s0 += fv * Wsm[(kb + t) * 2 + 0];
            s1 += fv * Wsm[(kb + t) * 2 + 1];
            n0 += xv * Wnews[(kb + t) * 2 + 0];
            n1 += xv * Wnews[(kb + t) * 2 + 1];
        }
#pragma unroll
        for (int off = 16; off > 0; off >>= 1) {
            s0 += __shfl_down_sync(0xffffffffu, s0, off);
            s1 += __shfl_down_sync(0xffffffffu, s1, off);
            n0 += __shfl_down_sync(0xffffffffu, n0, off);
            n1 += __shfl_down_sync(0xffffffffu, n1, off);
        }
        if (tid == 0) {
            float h0 = fmaxf(s0 + bsm[0], 0.f);
            float h1 = fmaxf(s1 + bsm[1], 0.f);
            float m0 = fmaxf(n0 + bnews[0], 0.f);
            float m1 = fmaxf(n1 + bnews[1], 0.f);
            float z = h0 * Wcat[0] + h1 * Wcat[1] + m0 * Wcat[2] + m1 * Wcat[3] + bcat[0];
            out[g] = 1.0f / (1.0f + expf(-z));
        }
    }
}

// ---------------- launch ----------------
extern "C" void kernel_launch(void* const* d_in, const int* in_sizes, int n_in,
                              void* d_out, int out_size) {
    const float* x     = (const float*)d_in[0];
    const int*   ei    = (const int*)d_in[1];
    const int*   src   = ei;
    const int*   dst   = ei + EE;
    const int*   batch = (const int*)d_in[2];
    const float* Wl1 = (const float*)d_in[3];
    const float* Wr1 = (const float*)d_in[4];
    const float* bl1 = (const float*)d_in[5];
    const float* Wl2 = (const float*)d_in[6];
    const float* Wr2 = (const float*)d_in[7];
    const float* bl2 = (const float*)d_in[8];
    const float* Wl3 = (const float*)d_in[9];
    const float* Wr3 = (const float*)d_in[10];
    const float* bl3 = (const float*)d_in[11];
    const float* W_f1 = (const float*)d_in[12];
    const float* b_f1 = (const float*)d_in[13];
    const float* W_f2 = (const float*)d_in[14];
    const float* b_f2 = (const float*)d_in[15];
    const float* W_sm = (const float*)d_in[16];
    const float* b_sm = (const float*)d_in[17];
    const float* W_news = (const float*)d_in[18];
    const float* b_news = (const float*)d_in[19];
    const float* W_cat = (const float*)d_in[20];
    const float* b_cat = (const float*)d_in[21];
    float* out = (float*)d_out;

    float *mean, *h1, *h2;
    uint4* wfrag;
    cudaGetSymbolAddress((void**)&mean, g_mean);
    cudaGetSymbolAddress((void**)&h1, g_h1);
    cudaGetSymbolAddress((void**)&h2, g_h2);
    cudaGetSymbolAddress((void**)&wfrag, g_Wfrag);

    const int TB = 256;
    const int gN = (NN + TB - 1) / TB;
    const int gE = (EE + TB - 1) / TB;

    // CSR build + roots + weight fragment prep
    k_init<<<gN, TB>>>(batch);
    k_prepW<<<(3 * 16 * 16 * 32 + TB - 1) / TB, TB>>>(Wl1, Wr1, Wl2, Wr2, Wl3, Wr3);
    k_hist<<<gE, TB>>>(dst);
    k_scan_blk<<<SCAN_BLKS, 1024>>>();
    k_scan_top<<<1, 64>>>();
    k_scan_add<<<SCAN_BLKS, 1024>>>();
    k_fill<<<gE, TB>>>(src, dst);

    const int gAgg = (NN * 32 + TB - 1) / TB;  // warp per node
    const int gGemm = (NN + 127) / 128;        // 391

    // layer 1: x -> h1
    k_aggregate<<<gAgg, TB>>>(x, mean);
    k_gemm_mma<<<gGemm, TB>>>(mean, x, wfrag, bl1, h1);
    // layer 2: h1 -> h2
    k_aggregate<<<gAgg, TB>>>(h1, mean);
    k_gemm_mma<<<gGemm, TB>>>(mean, h1, wfrag + 8192, bl2, h2);
    // layer 3: h2 -> h1
    k_aggregate<<<gAgg, TB>>>(h2, mean);
    k_gemm_mma<<<gGemm, TB>>>(mean, h2, wfrag + 16384, bl3, h1);

    // pooled head (fused)
    k_pool_mlp1<<<BG, 256>>>(h1, W_f1, b_f1);
    k_mlp2_final<<<BG, 128>>>(x, W_f2, b_f2, W_sm, b_sm, W_news, b_news,
                              W_cat, b_cat, out);
}

// round 11
// speedup vs baseline: 1.9006x; 1.0299x over previous
#include <cuda_runtime.h>
#include <cuda_bf16.h>
#include <math.h>
#include <stdint.h>

#define NN 50000
#define EE 800000
#define BG 512
#define D  128
#define SCAN_BLKS 49   // ceil(50000 / 1024)

// ---------------- scratch (static device globals; no allocation) ----------------
__device__ int   g_deg[NN];
__device__ int   g_rowptr[NN + 1];
__device__ int   g_cursor[NN];
__device__ int   g_col[EE];
__device__ int   g_root[BG + 1];
__device__ int   g_bsum[SCAN_BLKS];
__device__ int   g_boff[SCAN_BLKS];
__device__ int   g_scnt;   // scan arrival counter (reset each launch)
__device__ int   g_sgo;    // scan top-done flag (reset each launch)
__device__ float g_mean[NN * D];
__device__ float g_h1[NN * D];
__device__ float g_h2[NN * D];
// W in per-thread mma-fragment layout: [layer][k_step 16][n_atom 16][lane 32]
// each uint4 = {bh0, bh1, bl0, bl1}
__device__ uint4 g_Wfrag[3 * 16 * 16 * 32];

// ---------------- fused init: zero deg, roots, scan flags, W fragment prep ----------------
__global__ void k_initprep(const int* __restrict__ batch,
                           const float* __restrict__ Wl1, const float* __restrict__ Wr1,
                           const float* __restrict__ Wl2, const float* __restrict__ Wr2,
                           const float* __restrict__ Wl3, const float* __restrict__ Wr3) {
    int i = blockIdx.x * blockDim.x + threadIdx.x;
    if (i < NN) {
        g_deg[i] = 0;
        int b = batch[i];
        if (i == 0 || batch[i - 1] != b) g_root[b] = i;
        if (i == 0) { g_root[BG] = NN; g_scnt = 0; g_sgo = 0; }
    }
    if (i < 3 * 16 * 16 * 32) {
        int L    = i >> 13;
        int rem  = i & 8191;
        int t    = rem >> 9;          // k_step 0..15
        int na   = (rem >> 5) & 15;   // n_atom 0..15
        int lane = rem & 31;
        const float* Wl = (L == 0) ? Wl1 : (L == 1) ? Wl2 : Wl3;
        const float* Wr = (L == 0) ? Wr1 : (L == 1) ? Wr2 : Wr3;
        int n  = na * 8 + (lane >> 2);
        int k0 = t * 16 + (lane & 3) * 2;
        float w[4];
#pragma unroll
        for (int q = 0; q < 4; q++) {
            int k = k0 + (q >> 1) * 8 + (q & 1);  // k0, k0+1, k0+8, k0+9
            w[q] = (k < 128) ? Wl[k * 128 + n] : Wr[(k - 128) * 128 + n];
        }
        unsigned short h[4], l[4];
#pragma unroll
        for (int q = 0; q < 4; q++) {
            __nv_bfloat16 hb = __float2bfloat16(w[q]);
            __nv_bfloat16 lb = __float2bfloat16(w[q] - __bfloat162float(hb));
            h[q] = __bfloat16_as_ushort(hb);
            l[q] = __bfloat16_as_ushort(lb);
        }
        uint4 v;
        v.x = (uint32_t)h[0] | ((uint32_t)h[1] << 16);
        v.y = (uint32_t)h[2] | ((uint32_t)h[3] << 16);
        v.z = (uint32_t)l[0] | ((uint32_t)l[1] << 16);
        v.w = (uint32_t)l[2] | ((uint32_t)l[3] << 16);
        g_Wfrag[i] = v;
    }
}

__global__ void k_hist(const int* __restrict__ dst) {
    int e = blockIdx.x * blockDim.x + threadIdx.x;
    if (e < EE) atomicAdd(&g_deg[dst[e]], 1);
}

// ---------------- single-kernel scan: local scans + resident global barrier ----------------
// 49 blocks (< 148 SMs, all resident). Last-arriving block scans block sums; others
// spin on g_sgo. ALL __syncthreads() are executed by every thread of the block.
__global__ void k_scan_one() {
    __shared__ int sc[1024];
    __shared__ int s_last;
    __shared__ int s_boff;
    __shared__ int tops[64];
    int t = threadIdx.x;
    int bid = blockIdx.x;
    int i = bid * 1024 + t;
    int d = (i < NN) ? g_deg[i] : 0;
    sc[t] = d;
    __syncthreads();
#pragma unroll
    for (int off = 1; off < 1024; off <<= 1) {
        int add = (t >= off) ? sc[t - off] : 0;
        __syncthreads();
        sc[t] += add;
        __syncthreads();
    }
    int excl = sc[t] - d;               // exclusive within block
    if (t == 1023) g_bsum[bid] = sc[1023];
    __syncthreads();
    // arrive (fence makes g_bsum visible at L2 before the count bump)
    if (t == 0) {
        __threadfence();
        int a = atomicAdd(&g_scnt, 1);
        s_last = (a == SCAN_BLKS - 1) ? 1 : 0;
    }
    __syncthreads();
    if (s_last) {
        // last block: scan the 49 block sums. volatile loads bypass L1.
        if (t < 64) tops[t] = (t < SCAN_BLKS) ? *(volatile int*)&g_bsum[t] : 0;
        __syncthreads();
#pragma unroll
        for (int off = 1; off < 64; off <<= 1) {
            int add = (t < 64 && t >= off) ? tops[t - off] : 0;
            __syncthreads();
            if (t < 64) tops[t] += add;
            __syncthreads();
        }
        if (t < SCAN_BLKS) g_boff[t] = tops[t] - *(volatile int*)&g_bsum[t];
        if (t == SCAN_BLKS - 1) g_rowptr[NN] = tops[t];
        __syncthreads();
        if (t == 0) {
            __threadfence();
            atomicExch(&g_sgo, 1);
        }
    }
    // all blocks: wait for top-scan, then fetch this block's offset (volatile, post-fence)
    if (t == 0) {
        while (atomicAdd(&g_sgo, 0) == 0) { }
        s_boff = *(volatile int*)&g_boff[bid];
    }
    __syncthreads();
    if (i < NN) {
        int v = excl + s_boff;
        g_rowptr[i] = v;
        g_cursor[i] = v;
    }
}

__global__ void k_fill(const int* __restrict__ src, const int* __restrict__ dst) {
    int e = blockIdx.x * blockDim.x + threadIdx.x;
    if (e < EE) {
        int d = dst[e];
        int p = atomicAdd(&g_cursor[d], 1);
        g_col[p] = src[e];
    }
}

// ---------------- mean aggregation: warp per node, lane = one float4, 4-way unroll ----------------
__global__ void k_aggregate(const float* __restrict__ feat, float* __restrict__ mean) {
    int warp = (blockIdx.x * blockDim.x + threadIdx.x) >> 5;
    int lane = threadIdx.x & 31;
    if (warp >= NN) return;
    int s = g_rowptr[warp];
    int e = g_rowptr[warp + 1];
    float4 acc = make_float4(0.f, 0.f, 0.f, 0.f);
    const float4* f4 = (const float4*)feat;
    int i = s;
    for (; i + 4 <= e; i += 4) {
        int c0 = __ldg(&g_col[i]);
        int c1 = __ldg(&g_col[i + 1]);
        int c2 = __ldg(&g_col[i + 2]);
        int c3 = __ldg(&g_col[i + 3]);
        float4 v0 = __ldg(&f4[c0 * 32 + lane]);
        float4 v1 = __ldg(&f4[c1 * 32 + lane]);
        float4 v2 = __ldg(&f4[c2 * 32 + lane]);
        float4 v3 = __ldg(&f4[c3 * 32 + lane]);
        acc.x += v0.x + v1.x + v2.x + v3.x;
        acc.y += v0.y + v1.y + v2.y + v3.y;
        acc.z += v0.z + v1.z + v2.z + v3.z;
        acc.w += v0.w + v1.w + v2.w + v3.w;
    }
    for (; i < e; i++) {
        int c = __ldg(&g_col[i]);
        float4 v = __ldg(&f4[c * 32 + lane]);
        acc.x += v.x; acc.y += v.y; acc.z += v.z; acc.w += v.w;
    }
    int cnt = e - s;
    float inv = 1.0f / (float)(cnt > 0 ? cnt : 1);
    acc.x *= inv; acc.y *= inv; acc.z *= inv; acc.w *= inv;
    ((float4*)mean)[warp * 32 + lane] = acc;
}

// ---------------- tensor-core SAGE GEMM ----------------
// out[128 rows tile][128] = relu([mean|feat] @ W + bias), K = 256.
// 3-term bf16 split: D = Ah*Bh + Ah*Bl + Al*Bh (fp32 accumulate).
// 8 warps: warp_row (2) x warp_col (4); warp tile 64x32.
#define APITCH 36

__device__ __forceinline__ void mma_bf16(float* c, const uint32_t* a,
                                         uint32_t b0, uint32_t b1) {
    asm("mma.sync.aligned.m16n8k16.row.col.f32.bf16.bf16.f32 "
        "{%0,%1,%2,%3}, {%4,%5,%6,%7}, {%8,%9}, {%0,%1,%2,%3};"
        : "+f"(c[0]), "+f"(c[1]), "+f"(c[2]), "+f"(c[3])
        : "r"(a[0]), "r"(a[1]), "r"(a[2]), "r"(a[3]), "r"(b0), "r"(b1));
}

__global__ __launch_bounds__(256)
void k_gemm_mma(const float* __restrict__ Amean, const float* __restrict__ Afeat,
                const uint4* __restrict__ Wfrag, const float* __restrict__ bias,
                float* __restrict__ out) {
    __shared__ uint32_t sAhi[128 * APITCH];
    __shared__ uint32_t sAlo[128 * APITCH];

    const int tid  = threadIdx.x;
    const int wid  = tid >> 5;
    const int lane = tid & 31;
    const int wr = wid >> 2;           // 0..1
    const int wc = wid & 3;            // 0..3
    const int row0 = blockIdx.x * 128;

    float acc[4][4][4];
#pragma unroll
    for (int i = 0; i < 4; i++)
#pragma unroll
        for (int j = 0; j < 4; j++)
#pragma unroll
            for (int r = 0; r < 4; r++) acc[i][j][r] = 0.f;

    for (int chunk = 0; chunk < 4; chunk++) {
        const float* A = (chunk < 2) ? Amean : Afeat;
        const int kb = (chunk & 1) * 64;

        // ---- stage A chunk: 128 rows x 64 k -> bf16 hi/lo smem images ----
        {
            int r = tid >> 1;
            int half = tid & 1;
            int grow = row0 + r;
            const float4* Ag = (const float4*)(A + (size_t)grow * D + kb);
#pragma unroll
            for (int q = 0; q < 8; q++) {
                float4 v = make_float4(0.f, 0.f, 0.f, 0.f);
                if (grow < NN) v = __ldg(&Ag[half * 8 + q]);
                __nv_bfloat16 hx = __float2bfloat16(v.x);
                __nv_bfloat16 hy = __float2bfloat16(v.y);
                __nv_bfloat16 hz = __float2bfloat16(v.z);
                __nv_bfloat16 hw = __float2bfloat16(v.w);
                uint2 hv, lv;
                hv.x = (uint32_t)__bfloat16_as_ushort(hx) |
                       ((uint32_t)__bfloat16_as_ushort(hy) << 16);
                hv.y = (uint32_t)__bfloat16_as_ushort(hz) |
                       ((uint32_t)__bfloat16_as_ushort(hw) << 16);
                __nv_bfloat16 lx = __float2bfloat16(v.x - __bfloat162float(hx));
                __nv_bfloat16 ly = __float2bfloat16(v.y - __bfloat162float(hy));
                __nv_bfloat16 lz = __float2bfloat16(v.z - __bfloat162float(hz));
                __nv_bfloat16 lw = __float2bfloat16(v.w - __bfloat162float(hw));
                lv.x = (uint32_t)__bfloat16_as_ushort(lx) |
                       ((uint32_t)__bfloat16_as_ushort(ly) << 16);
                lv.y = (uint32_t)__bfloat16_as_ushort(lz) |
                       ((uint32_t)__bfloat16_as_ushort(lw) << 16);
                int c = half * 16 + q * 2;
                *(uint2*)&sAhi[r * APITCH + c] = hv;
                *(uint2*)&sAlo[r * APITCH + c] = lv;
            }
        }
        __syncthreads();

        // ---- mma over 4 k-steps of 16 ----
#pragma unroll
        for (int t = 0; t < 4; t++) {
            uint4 B[4];
#pragma unroll
            for (int j = 0; j < 4; j++)
                B[j] = __ldg(&Wfrag[(((chunk * 4 + t) * 16) + (wc * 4 + j)) * 32 + lane]);

            const int rb = wr * 64 + (lane >> 2);
            const int cw = t * 8 + (lane & 3);
#pragma unroll
            for (int i = 0; i < 4; i++) {
                int base = (rb + i * 16) * APITCH;
                uint32_t ah[4], al[4];
                ah[0] = sAhi[base + cw];
                ah[1] = sAhi[base + 8 * APITCH + cw];
                ah[2] = sAhi[base + cw + 4];
                ah[3] = sAhi[base + 8 * APITCH + cw + 4];
                al[0] = sAlo[base + cw];
                al[1] = sAlo[base + 8 * APITCH + cw];
                al[2] = sAlo[base + cw + 4];
                al[3] = sAlo[base + 8 * APITCH + cw + 4];
#pragma unroll
                for (int j = 0; j < 4; j++) {
                    mma_bf16(acc[i][j], ah, B[j].x, B[j].y);  // Ah*Bh
                    mma_bf16(acc[i][j], ah, B[j].z, B[j].w);  // Ah*Bl
                    mma_bf16(acc[i][j], al, B[j].x, B[j].y);  // Al*Bh
                }
            }
        }
        __syncthreads();
    }

    // ---- epilogue: bias + relu, float2 stores ----
#pragma unroll
    for (int j = 0; j < 4; j++) {
        int col = wc * 32 + j * 8 + (lane & 3) * 2;
        float b0 = __ldg(&bias[col]);
        float b1 = __ldg(&bias[col + 1]);
#pragma unroll
        for (int i = 0; i < 4; i++) {
            int row = row0 + wr * 64 + i * 16 + (lane >> 2);
            if (row < NN) {
                float2 v0;
                v0.x = fmaxf(acc[i][j][0] + b0, 0.f);
                v0.y = fmaxf(acc[i][j][1] + b1, 0.f);
                *(float2*)(out + (size_t)row * D + col) = v0;
            }
            if (row + 8 < NN) {
                float2 v1;
                v1.x = fmaxf(acc[i][j][2] + b0, 0.f);
                v1.y = fmaxf(acc[i][j][3] + b1, 0.f);
                *(float2*)(out + (size_t)(row + 8) * D + col) = v1;
            }
        }
    }
}

// ---------------- fully fused tail: max-pool -> mlp1 -> mlp2 -> head ----------------
__global__ void k_tail(const float* __restrict__ h, const float* __restrict__ x,
                       const float* __restrict__ W1, const float* __restrict__ b1,
                       const float* __restrict__ W2, const float* __restrict__ b2,
                       const float* __restrict__ Wsm, const float* __restrict__ bsm,
                       const float* __restrict__ Wnews, const float* __restrict__ bnews,
                       const float* __restrict__ Wcat, const float* __restrict__ bcat,
                       float* __restrict__ out) {
    __shared__ float pool[128];
    __shared__ float pmax[256];
    __shared__ float f1s[256];
    __shared__ float f2s[128];
    __shared__ float xroot[128];
    int g = blockIdx.x;
    int tid = threadIdx.x;  // 0..255
    int col = tid & 127, half = tid >> 7;
    int s = g_root[g], e = g_root[g + 1];
    float m = -3.4e38f;
    for (int n = s + half; n < e; n += 2) m = fmaxf(m, h[(size_t)n * D + col]);
    pmax[tid] = m;
    __syncthreads();
    if (tid < 128) {
        pool[tid] = fmaxf(pmax[tid], pmax[tid + 128]);
        xroot[tid] = x[(size_t)s * D + tid];   // root = first node of graph (batch sorted)
    }
    __syncthreads();
    // mlp1: 256 outputs
    float a1 = b1[tid];
#pragma unroll 16
    for (int k = 0; k < 128; k++) a1 += pool[k] * W1[k * 256 + tid];
    f1s[tid] = fmaxf(a1, 0.f);
    __syncthreads();
    // mlp2: 128 outputs
    if (tid < 128) {
        float a2 = b2[tid];
#pragma unroll 16
        for (int k = 0; k < 256; k++) a2 += f1s[k] * W2[k * 128 + tid];
        f2s[tid] = fmaxf(a2, 0.f);
    }
    __syncthreads();
    // head: 1 warp
    if (tid < 32) {
        int kb = tid * 4;
        float s0 = 0.f, s1 = 0.f, n0 = 0.f, n1 = 0.f;
#pragma unroll
        for (int t = 0; t < 4; t++) {
            float fv = f2s[kb + t];
            float xv = xroot[kb + t];
            s0 += fv * Wsm[(kb + t) * 2 + 0];
            s1 += fv * Wsm[(kb + t) * 2 + 1];
            n0 += xv * Wnews[(kb + t) * 2 + 0];
            n1 += xv * Wnews[(kb + t) * 2 + 1];
        }
#pragma unroll
        for (int off = 16; off > 0; off >>= 1) {
            s0 += __shfl_down_sync(0xffffffffu, s0, off);
            s1 += __shfl_down_sync(0xffffffffu, s1, off);
            n0 += __shfl_down_sync(0xffffffffu, n0, off);
            n1 += __shfl_down_sync(0xffffffffu, n1, off);
        }
        if (tid == 0) {
            float h0 = fmaxf(s0 + bsm[0], 0.f);
            float h1 = fmaxf(s1 + bsm[1], 0.f);
            float m0 = fmaxf(n0 + bnews[0], 0.f);
            float m1 = fmaxf(n1 + bnews[1], 0.f);
            float z = h0 * Wcat[0] + h1 * Wcat[1] + m0 * Wcat[2] + m1 * Wcat[3] + bcat[0];
            out[g] = 1.0f / (1.0f + expf(-z));
        }
    }
}

// ---------------- launch ----------------
extern "C" void kernel_launch(void* const* d_in, const int* in_sizes, int n_in,
                              void* d_out, int out_size) {
    const float* x     = (const float*)d_in[0];
    const int*   ei    = (const int*)d_in[1];
    const int*   src   = ei;
    const int*   dst   = ei + EE;
    const int*   batch = (const int*)d_in[2];
    const float* Wl1 = (const float*)d_in[3];
    const float* Wr1 = (const float*)d_in[4];
    const float* bl1 = (const float*)d_in[5];
    const float* Wl2 = (const float*)d_in[6];
    const float* Wr2 = (const float*)d_in[7];
    const float* bl2 = (const float*)d_in[8];
    const float* Wl3 = (const float*)d_in[9];
    const float* Wr3 = (const float*)d_in[10];
    const float* bl3 = (const float*)d_in[11];
    const float* W_f1 = (const float*)d_in[12];
    const float* b_f1 = (const float*)d_in[13];
    const float* W_f2 = (const float*)d_in[14];
    const float* b_f2 = (const float*)d_in[15];
    const float* W_sm = (const float*)d_in[16];
    const float* b_sm = (const float*)d_in[17];
    const float* W_news = (const float*)d_in[18];
    const float* b_news = (const float*)d_in[19];
    const float* W_cat = (const float*)d_in[20];
    const float* b_cat = (const float*)d_in[21];
    float* out = (float*)d_out;

    float *mean, *h1, *h2;
    uint4* wfrag;
    cudaGetSymbolAddress((void**)&mean, g_mean);
    cudaGetSymbolAddress((void**)&h1, g_h1);
    cudaGetSymbolAddress((void**)&h2, g_h2);
    cudaGetSymbolAddress((void**)&wfrag, g_Wfrag);

    const int TB = 256;
    const int gN = (NN + TB - 1) / TB;
    const int gE = (EE + TB - 1) / TB;

    // CSR build + roots + weight fragment prep
    k_initprep<<<gN, TB>>>(batch, Wl1, Wr1, Wl2, Wr2, Wl3, Wr3);
    k_hist<<<gE, TB>>>(dst);
    k_scan_one<<<SCAN_BLKS, 1024>>>();
    k_fill<<<gE, TB>>>(src, dst);

    const int gAgg = (NN * 32 + TB - 1) / TB;  // warp per node
    const int gGemm = (NN + 127) / 128;        // 391

    // layer 1: x -> h1
    k_aggregate<<<gAgg, TB>>>(x, mean);
    k_gemm_mma<<<gGemm, TB>>>(mean, x, wfrag, bl1, h1);
    // layer 2: h1 -> h2
    k_aggregate<<<gAgg, TB>>>(h1, mean);
    k_gemm_mma<<<gGemm, TB>>>(mean, h1, wfrag + 8192, bl2, h2);
    // layer 3: h2 -> h1
    k_aggregate<<<gAgg, TB>>>(h2, mean);
    k_gemm_mma<<<gGemm, TB>>>(mean, h2, wfrag + 16384, bl3, h1);

    // fused tail
    k_tail<<<BG, TB>>>(h1, x, W_f1, b_f1, W_f2, b_f2, W_sm, b_sm,
                       W_news, b_news, W_cat, b_cat, out);
}